// round 1
// baseline (speedup 1.0000x reference)
#include <cuda_runtime.h>
#include <cuda_bf16.h>
#include <math.h>

// Block: B=1, T=4096, C=1024, H=16, hs=64
#define SEQ 4096
#define EMB 1024
#define NHEAD 16
#define HS 64
#define C3 3072
#define CFC 4096

// ---------------- device scratch (no allocations allowed) ----------------
__device__ float g_h[SEQ * EMB];       // LN output (reused for both LNs)
__device__ float g_qkv[SEQ * C3];      // qkv
__device__ float g_attn[SEQ * EMB];    // attention output (pre-proj)
__device__ float g_x1[SEQ * EMB];      // x + attn_proj
__device__ float g_fc[SEQ * CFC];      // gelu(fc)

// ---------------- LayerNorm: one block per row ----------------
__global__ void ln_kernel(const float* __restrict__ x,
                          const float* __restrict__ w,
                          float* __restrict__ out) {
    const int row = blockIdx.x;
    const int tid = threadIdx.x;           // 256 threads, 4 floats each
    const float4 v = reinterpret_cast<const float4*>(x + (size_t)row * EMB)[tid];

    float s = v.x + v.y + v.z + v.w;
    float q = v.x * v.x + v.y * v.y + v.z * v.z + v.w * v.w;
    #pragma unroll
    for (int off = 16; off > 0; off >>= 1) {
        s += __shfl_xor_sync(0xffffffffu, s, off);
        q += __shfl_xor_sync(0xffffffffu, q, off);
    }
    __shared__ float ws[8], wq[8];
    __shared__ float s_mean, s_rstd;
    const int wid = tid >> 5, lane = tid & 31;
    if (lane == 0) { ws[wid] = s; wq[wid] = q; }
    __syncthreads();
    if (tid == 0) {
        float S = 0.f, Q = 0.f;
        #pragma unroll
        for (int i = 0; i < 8; i++) { S += ws[i]; Q += wq[i]; }
        float mean = S * (1.0f / EMB);
        float var = Q * (1.0f / EMB) - mean * mean;
        s_mean = mean;
        s_rstd = rsqrtf(var + 1e-5f);
    }
    __syncthreads();
    const float mean = s_mean, rstd = s_rstd;
    const float4 g = reinterpret_cast<const float4*>(w)[tid];
    float4 o;
    o.x = (v.x - mean) * rstd * g.x;
    o.y = (v.y - mean) * rstd * g.y;
    o.z = (v.z - mean) * rstd * g.z;
    o.w = (v.w - mean) * rstd * g.w;
    reinterpret_cast<float4*>(out + (size_t)row * EMB)[tid] = o;
}

// ---------------- GEMM: C[M,N] = A[M,K] @ B[K,N], fp32, 128x128x16 tile ----------------
// EPI: 0 = plain, 1 = C = R + A@B (residual), 2 = C = gelu(A@B)
__device__ __forceinline__ float gelu_exact(float v) {
    return 0.5f * v * (1.0f + erff(v * 0.70710678118654752440f));
}

template <int EPI>
__global__ __launch_bounds__(256) void gemm_kernel(
    const float* __restrict__ A, const float* __restrict__ B,
    const float* __restrict__ R, float* __restrict__ C,
    int M, int N, int K) {
    __shared__ float As[16][128];   // [k][m]  (A staged transposed)
    __shared__ float Bs[16][128];   // [k][n]

    const int tid = threadIdx.x;
    const int tx = tid & 15;        // 16
    const int ty = tid >> 4;        // 16
    const int bm = blockIdx.y * 128;
    const int bn = blockIdx.x * 128;

    float acc[8][8];
    #pragma unroll
    for (int i = 0; i < 8; i++)
        #pragma unroll
        for (int j = 0; j < 8; j++) acc[i][j] = 0.f;

    for (int k0 = 0; k0 < K; k0 += 16) {
        #pragma unroll
        for (int i = 0; i < 2; i++) {
            const int lin = tid + i * 256;
            // A: 128 rows x 16 k  -> 512 float4
            const int r = lin >> 2;
            const int c = (lin & 3) << 2;
            const float4 a = *reinterpret_cast<const float4*>(
                A + (size_t)(bm + r) * K + k0 + c);
            As[c + 0][r] = a.x;
            As[c + 1][r] = a.y;
            As[c + 2][r] = a.z;
            As[c + 3][r] = a.w;
            // B: 16 rows x 128 n -> 512 float4
            const int kr = lin >> 5;
            const int bc = (lin & 31) << 2;
            *reinterpret_cast<float4*>(&Bs[kr][bc]) =
                *reinterpret_cast<const float4*>(B + (size_t)(k0 + kr) * N + bn + bc);
        }
        __syncthreads();

        #pragma unroll
        for (int kk = 0; kk < 16; kk++) {
            float a[8], b[8];
            *reinterpret_cast<float4*>(a)     = *reinterpret_cast<float4*>(&As[kk][ty * 8]);
            *reinterpret_cast<float4*>(a + 4) = *reinterpret_cast<float4*>(&As[kk][ty * 8 + 4]);
            *reinterpret_cast<float4*>(b)     = *reinterpret_cast<float4*>(&Bs[kk][tx * 8]);
            *reinterpret_cast<float4*>(b + 4) = *reinterpret_cast<float4*>(&Bs[kk][tx * 8 + 4]);
            #pragma unroll
            for (int i = 0; i < 8; i++)
                #pragma unroll
                for (int j = 0; j < 8; j++)
                    acc[i][j] = fmaf(a[i], b[j], acc[i][j]);
        }
        __syncthreads();
    }

    // epilogue, vectorized float4 stores
    #pragma unroll
    for (int i = 0; i < 8; i++) {
        const size_t m = (size_t)(bm + ty * 8 + i);
        #pragma unroll
        for (int j4 = 0; j4 < 2; j4++) {
            const int n = bn + tx * 8 + j4 * 4;
            float4 v;
            v.x = acc[i][j4 * 4 + 0];
            v.y = acc[i][j4 * 4 + 1];
            v.z = acc[i][j4 * 4 + 2];
            v.w = acc[i][j4 * 4 + 3];
            if (EPI == 1) {
                const float4 r = *reinterpret_cast<const float4*>(R + m * N + n);
                v.x += r.x; v.y += r.y; v.z += r.z; v.w += r.w;
            } else if (EPI == 2) {
                v.x = gelu_exact(v.x); v.y = gelu_exact(v.y);
                v.z = gelu_exact(v.z); v.w = gelu_exact(v.w);
            }
            *reinterpret_cast<float4*>(C + m * N + n) = v;
        }
    }
}

// ---------------- Flash attention (causal), 64q x 64k tiles, hs=64 ----------------
// Block: 256 threads = 16x16, each owns 4x4 of the 64x64 tiles.
// smem (dynamic): Qs[64][68] k-major, Ks[64][68] k-major, Vs[64][68] row-major, Ps[64][68] k-major
#define FPAD 68

__global__ __launch_bounds__(256) void flash_kernel(
    const float* __restrict__ qkv, float* __restrict__ out) {
    extern __shared__ float smf[];
    float* Qs = smf;
    float* Ks = smf + 64 * FPAD;
    float* Vs = smf + 2 * 64 * FPAD;
    float* Ps = smf + 3 * 64 * FPAD;

    const int tid = threadIdx.x;
    const int tx = tid & 15;
    const int ty = tid >> 4;
    const int qb = blockIdx.x;     // query tile (64 rows)
    const int h = blockIdx.y;      // head

    // ---- load Q tile (transposed: Qs[d][m]) ----
    {
        const int r0 = tid >> 4;            // 0..15
        const int c4 = (tid & 15) << 2;     // 0..60 (d offset)
        #pragma unroll
        for (int i = 0; i < 4; i++) {
            const int m = r0 + i * 16;
            const float4 q = *reinterpret_cast<const float4*>(
                qkv + (size_t)(qb * 64 + m) * C3 + h * HS + c4);
            Qs[(c4 + 0) * FPAD + m] = q.x;
            Qs[(c4 + 1) * FPAD + m] = q.y;
            Qs[(c4 + 2) * FPAD + m] = q.z;
            Qs[(c4 + 3) * FPAD + m] = q.w;
        }
    }

    float mi[4], li[4], o[4][4];
    #pragma unroll
    for (int i = 0; i < 4; i++) {
        mi[i] = -1e30f; li[i] = 0.f;
        #pragma unroll
        for (int j = 0; j < 4; j++) o[i][j] = 0.f;
    }

    for (int kt = 0; kt <= qb; kt++) {
        __syncthreads();   // protect Ks/Vs/Ps reuse
        // ---- load K (transposed) and V (row-major) tiles ----
        {
            const int r0 = tid >> 4;
            const int c4 = (tid & 15) << 2;
            #pragma unroll
            for (int i = 0; i < 4; i++) {
                const int n = r0 + i * 16;
                const size_t base = (size_t)(kt * 64 + n) * C3 + h * HS + c4;
                const float4 k = *reinterpret_cast<const float4*>(qkv + base + EMB);
                Ks[(c4 + 0) * FPAD + n] = k.x;
                Ks[(c4 + 1) * FPAD + n] = k.y;
                Ks[(c4 + 2) * FPAD + n] = k.z;
                Ks[(c4 + 3) * FPAD + n] = k.w;
                const float4 vv = *reinterpret_cast<const float4*>(qkv + base + 2 * EMB);
                *reinterpret_cast<float4*>(Vs + n * FPAD + c4) = vv;
            }
        }
        __syncthreads();

        // ---- S = Q @ K^T (scaled) ----
        float s[4][4];
        #pragma unroll
        for (int i = 0; i < 4; i++)
            #pragma unroll
            for (int j = 0; j < 4; j++) s[i][j] = 0.f;
        #pragma unroll 8
        for (int kk = 0; kk < 64; kk++) {
            float a[4], b[4];
            *reinterpret_cast<float4*>(a) = *reinterpret_cast<float4*>(Qs + kk * FPAD + ty * 4);
            *reinterpret_cast<float4*>(b) = *reinterpret_cast<float4*>(Ks + kk * FPAD + tx * 4);
            #pragma unroll
            for (int i = 0; i < 4; i++)
                #pragma unroll
                for (int j = 0; j < 4; j++)
                    s[i][j] = fmaf(a[i], b[j], s[i][j]);
        }
        const bool diag = (kt == qb);
        #pragma unroll
        for (int i = 0; i < 4; i++)
            #pragma unroll
            for (int j = 0; j < 4; j++) {
                s[i][j] *= 0.125f;  // 1/sqrt(64)
                if (diag && (tx * 4 + j) > (ty * 4 + i)) s[i][j] = -1e30f;
            }

        // ---- online softmax row stats (16 threads per row: shuffle over tx) ----
        #pragma unroll
        for (int i = 0; i < 4; i++) {
            float mx = fmaxf(fmaxf(s[i][0], s[i][1]), fmaxf(s[i][2], s[i][3]));
            #pragma unroll
            for (int off = 8; off > 0; off >>= 1)
                mx = fmaxf(mx, __shfl_xor_sync(0xffffffffu, mx, off));
            const float mn = fmaxf(mi[i], mx);
            const float alpha = __expf(mi[i] - mn);
            float rs = 0.f;
            #pragma unroll
            for (int j = 0; j < 4; j++) {
                const float p = __expf(s[i][j] - mn);
                s[i][j] = p;
                rs += p;
            }
            #pragma unroll
            for (int off = 8; off > 0; off >>= 1)
                rs += __shfl_xor_sync(0xffffffffu, rs, off);
            li[i] = li[i] * alpha + rs;
            mi[i] = mn;
            #pragma unroll
            for (int j = 0; j < 4; j++) o[i][j] *= alpha;
            // write P transposed: Ps[k][m]
            #pragma unroll
            for (int j = 0; j < 4; j++)
                Ps[(tx * 4 + j) * FPAD + ty * 4 + i] = s[i][j];
        }
        __syncthreads();

        // ---- O += P @ V ----
        #pragma unroll 8
        for (int kk = 0; kk < 64; kk++) {
            float p[4], v[4];
            *reinterpret_cast<float4*>(p) = *reinterpret_cast<float4*>(Ps + kk * FPAD + ty * 4);
            *reinterpret_cast<float4*>(v) = *reinterpret_cast<float4*>(Vs + kk * FPAD + tx * 4);
            #pragma unroll
            for (int i = 0; i < 4; i++)
                #pragma unroll
                for (int j = 0; j < 4; j++)
                    o[i][j] = fmaf(p[i], v[j], o[i][j]);
        }
    }

    // ---- finalize and store: out[q][h*64+d] ----
    #pragma unroll
    for (int i = 0; i < 4; i++) {
        const float inv = 1.0f / li[i];
        const size_t row = (size_t)(qb * 64 + ty * 4 + i);
        float4 v;
        v.x = o[i][0] * inv; v.y = o[i][1] * inv;
        v.z = o[i][2] * inv; v.w = o[i][3] * inv;
        *reinterpret_cast<float4*>(out + row * EMB + h * HS + tx * 4) = v;
    }
}

// ---------------- launch ----------------
extern "C" void kernel_launch(void* const* d_in, const int* in_sizes, int n_in,
                              void* d_out, int out_size) {
    const float* x           = (const float*)d_in[0];
    const float* w_qkv       = (const float*)d_in[1];
    const float* w_attn_proj = (const float*)d_in[2];
    const float* w_fc        = (const float*)d_in[3];
    const float* w_mlp_proj  = (const float*)d_in[4];
    const float* ln1_w       = (const float*)d_in[5];
    const float* ln2_w       = (const float*)d_in[6];
    float* out = (float*)d_out;

    float *p_h, *p_qkv, *p_attn, *p_x1, *p_fc;
    cudaGetSymbolAddress((void**)&p_h, g_h);
    cudaGetSymbolAddress((void**)&p_qkv, g_qkv);
    cudaGetSymbolAddress((void**)&p_attn, g_attn);
    cudaGetSymbolAddress((void**)&p_x1, g_x1);
    cudaGetSymbolAddress((void**)&p_fc, g_fc);

    const int flash_smem = 4 * 64 * FPAD * (int)sizeof(float);  // 69,632 B
    cudaFuncSetAttribute(flash_kernel, cudaFuncAttributeMaxDynamicSharedMemorySize, flash_smem);

    // 1. h = LN(x, ln1)
    ln_kernel<<<SEQ, 256>>>(x, ln1_w, p_h);
    // 2. qkv = h @ w_qkv   [4096,1024]x[1024,3072]
    gemm_kernel<0><<<dim3(C3 / 128, SEQ / 128), 256>>>(p_h, w_qkv, nullptr, p_qkv, SEQ, C3, EMB);
    // 3. attention
    flash_kernel<<<dim3(SEQ / 64, NHEAD), 256, flash_smem>>>(p_qkv, p_attn);
    // 4. x1 = x + attn @ w_attn_proj
    gemm_kernel<1><<<dim3(EMB / 128, SEQ / 128), 256>>>(p_attn, w_attn_proj, x, p_x1, SEQ, EMB, EMB);
    // 5. h = LN(x1, ln2)
    ln_kernel<<<SEQ, 256>>>(p_x1, ln2_w, p_h);
    // 6. fc = gelu(h @ w_fc)
    gemm_kernel<2><<<dim3(CFC / 128, SEQ / 128), 256>>>(p_h, w_fc, nullptr, p_fc, SEQ, CFC, EMB);
    // 7. out = x1 + fc @ w_mlp_proj
    gemm_kernel<1><<<dim3(EMB / 128, SEQ / 128), 256>>>(p_fc, w_mlp_proj, p_x1, out, SEQ, EMB, CFC);
}

// round 3
// speedup vs baseline: 1.7461x; 1.7461x over previous
#include <cuda_runtime.h>
#include <cuda_bf16.h>
#include <mma.h>
#include <cstdint>
#include <math.h>

using namespace nvcuda;

// Block: B=1, T=4096, C=1024, H=16, hs=64
#define SEQ 4096
#define EMB 1024
#define NHEAD 16
#define HS 64
#define C3 3072
#define CFC 4096

typedef __nv_bfloat16 bf16;

// ---------------- device scratch (no allocations allowed) ----------------
__device__ bf16 g_h_hi[SEQ * EMB], g_h_lo[SEQ * EMB];        // LN out (split)
__device__ float g_qkv[SEQ * C3];                            // qkv fp32
__device__ bf16 g_attn_hi[SEQ * EMB], g_attn_lo[SEQ * EMB];  // attention out (split)
__device__ float g_x1[SEQ * EMB];                            // x + attn_proj
__device__ bf16 g_fc_hi[SEQ * CFC], g_fc_lo[SEQ * CFC];      // gelu(fc) (split)
// transposed + split weights: Wt[n][k]
__device__ bf16 g_wqkv_hi[C3 * EMB], g_wqkv_lo[C3 * EMB];
__device__ bf16 g_wproj_hi[EMB * EMB], g_wproj_lo[EMB * EMB];
__device__ bf16 g_wfc_hi[CFC * EMB], g_wfc_lo[CFC * EMB];
__device__ bf16 g_wmlp_hi[EMB * CFC], g_wmlp_lo[EMB * CFC];

__device__ __forceinline__ void split_bf16(float v, bf16& hi, bf16& lo) {
    hi = __float2bfloat16(v);
    lo = __float2bfloat16(v - __bfloat162float(hi));
}
__device__ __forceinline__ float gelu_exact(float v) {
    return 0.5f * v * (1.0f + erff(v * 0.70710678118654752440f));
}

// ---------------- LayerNorm -> split bf16 ----------------
__global__ void ln_kernel(const float* __restrict__ x, const float* __restrict__ w,
                          bf16* __restrict__ out_hi, bf16* __restrict__ out_lo) {
    const int row = blockIdx.x;
    const int tid = threadIdx.x;  // 256, 4 floats each
    const float4 v = reinterpret_cast<const float4*>(x + (size_t)row * EMB)[tid];

    float s = v.x + v.y + v.z + v.w;
    float q = v.x * v.x + v.y * v.y + v.z * v.z + v.w * v.w;
    #pragma unroll
    for (int off = 16; off > 0; off >>= 1) {
        s += __shfl_xor_sync(0xffffffffu, s, off);
        q += __shfl_xor_sync(0xffffffffu, q, off);
    }
    __shared__ float ws[8], wq[8], s_mean, s_rstd;
    const int wid = tid >> 5, lane = tid & 31;
    if (lane == 0) { ws[wid] = s; wq[wid] = q; }
    __syncthreads();
    if (tid == 0) {
        float S = 0.f, Q = 0.f;
        #pragma unroll
        for (int i = 0; i < 8; i++) { S += ws[i]; Q += wq[i]; }
        float mean = S * (1.0f / EMB);
        float var = Q * (1.0f / EMB) - mean * mean;
        s_mean = mean;
        s_rstd = rsqrtf(var + 1e-5f);
    }
    __syncthreads();
    const float mean = s_mean, rstd = s_rstd;
    const float4 g = reinterpret_cast<const float4*>(w)[tid];
    float o[4] = {(v.x - mean) * rstd * g.x, (v.y - mean) * rstd * g.y,
                  (v.z - mean) * rstd * g.z, (v.w - mean) * rstd * g.w};
    const size_t base = (size_t)row * EMB + tid * 4;
    #pragma unroll
    for (int i = 0; i < 4; i++) {
        bf16 hi, lo;
        split_bf16(o[i], hi, lo);
        out_hi[base + i] = hi;
        out_lo[base + i] = lo;
    }
}

// ---------------- weight transpose + split: W[K,N] fp32 -> Wt_hi/lo[N,K] bf16 ----------------
__global__ __launch_bounds__(256) void wt_split_kernel(const float* __restrict__ W,
                                                       bf16* __restrict__ th,
                                                       bf16* __restrict__ tl,
                                                       int K, int N) {
    __shared__ float tile[32][33];
    const int bn = blockIdx.x * 32;
    const int bk = blockIdx.y * 32;
    const int tx = threadIdx.x & 31, ty = threadIdx.x >> 5;
    #pragma unroll
    for (int r = ty; r < 32; r += 8)
        tile[r][tx] = W[(size_t)(bk + r) * N + bn + tx];
    __syncthreads();
    #pragma unroll
    for (int r = ty; r < 32; r += 8) {
        const float v = tile[tx][r];  // = W[bk+tx][bn+r]
        bf16 hi, lo;
        split_bf16(v, hi, lo);
        const size_t o = (size_t)(bn + r) * K + bk + tx;
        th[o] = hi;
        tl[o] = lo;
    }
}

// ---------------- WMMA GEMM: C[M,N] = A[M,K] @ Wt[N,K]^T, bf16x3, fp32 accum ----------------
// A hi/lo [M,K] row-major; B = Wt hi/lo [N,K] row-major (so matrix_b col_major over [K,N]).
// EPI: 0 = plain fp32 C, 1 = C = R + acc (acc initialized from R), 2 = gelu(acc)->split bf16
#define KC 64
#define APAD 72    // smem row stride in bf16 elems (144 B, multiple of 16 B)

template <int EPI>
__global__ __launch_bounds__(256, 2) void mma_gemm(
    const bf16* __restrict__ Ah, const bf16* __restrict__ Al,
    const bf16* __restrict__ Bh, const bf16* __restrict__ Bl,
    const float* __restrict__ R, float* __restrict__ C,
    bf16* __restrict__ Chi, bf16* __restrict__ Clo,
    int M, int N, int K) {
    extern __shared__ char smraw[];
    bf16* sAh = reinterpret_cast<bf16*>(smraw);
    bf16* sAl = sAh + 128 * APAD;
    bf16* sBh = sAl + 128 * APAD;
    bf16* sBl = sBh + 128 * APAD;

    const int tid = threadIdx.x;
    const int wid = tid >> 5;
    const int wm = wid & 1;        // 2 warps in M  (64 rows each)
    const int wn = wid >> 1;       // 4 warps in N  (32 cols each)
    const int bm = blockIdx.y * 128, bn = blockIdx.x * 128;

    wmma::fragment<wmma::accumulator, 16, 16, 16, float> acc[4][2];
    if (EPI == 1) {
        #pragma unroll
        for (int i = 0; i < 4; i++)
            #pragma unroll
            for (int j = 0; j < 2; j++)
                wmma::load_matrix_sync(
                    acc[i][j],
                    R + (size_t)(bm + wm * 64 + i * 16) * N + bn + wn * 32 + j * 16,
                    N, wmma::mem_row_major);
    } else {
        #pragma unroll
        for (int i = 0; i < 4; i++)
            #pragma unroll
            for (int j = 0; j < 2; j++)
                wmma::fill_fragment(acc[i][j], 0.0f);
    }

    const int c8 = tid & 7;        // 8 groups of 8 bf16 (16 B)
    const int r0 = tid >> 3;       // 0..31

    for (int k0 = 0; k0 < K; k0 += KC) {
        __syncthreads();
        #pragma unroll
        for (int rr = 0; rr < 4; rr++) {
            const int row = r0 + rr * 32;
            const size_t ga = (size_t)(bm + row) * K + k0 + c8 * 8;
            const size_t gb = (size_t)(bn + row) * K + k0 + c8 * 8;
            const int so = row * APAD + c8 * 8;
            *reinterpret_cast<float4*>(sAh + so) = *reinterpret_cast<const float4*>(Ah + ga);
            *reinterpret_cast<float4*>(sAl + so) = *reinterpret_cast<const float4*>(Al + ga);
            *reinterpret_cast<float4*>(sBh + so) = *reinterpret_cast<const float4*>(Bh + gb);
            *reinterpret_cast<float4*>(sBl + so) = *reinterpret_cast<const float4*>(Bl + gb);
        }
        __syncthreads();

        #pragma unroll
        for (int kk = 0; kk < KC / 16; kk++) {
            wmma::fragment<wmma::matrix_b, 16, 16, 16, bf16, wmma::col_major> b_hi[2], b_lo[2];
            #pragma unroll
            for (int j = 0; j < 2; j++) {
                const int nb = (wn * 32 + j * 16) * APAD + kk * 16;
                wmma::load_matrix_sync(b_hi[j], sBh + nb, APAD);
                wmma::load_matrix_sync(b_lo[j], sBl + nb, APAD);
            }
            #pragma unroll
            for (int i = 0; i < 4; i++) {
                wmma::fragment<wmma::matrix_a, 16, 16, 16, bf16, wmma::row_major> a_hi, a_lo;
                const int ab = (wm * 64 + i * 16) * APAD + kk * 16;
                wmma::load_matrix_sync(a_hi, sAh + ab, APAD);
                wmma::load_matrix_sync(a_lo, sAl + ab, APAD);
                #pragma unroll
                for (int j = 0; j < 2; j++) {
                    wmma::mma_sync(acc[i][j], a_hi, b_hi[j], acc[i][j]);
                    wmma::mma_sync(acc[i][j], a_hi, b_lo[j], acc[i][j]);
                    wmma::mma_sync(acc[i][j], a_lo, b_hi[j], acc[i][j]);
                }
            }
        }
    }

    if (EPI != 2) {
        // direct fp32 store (residual already folded into acc for EPI==1)
        #pragma unroll
        for (int i = 0; i < 4; i++)
            #pragma unroll
            for (int j = 0; j < 2; j++)
                wmma::store_matrix_sync(
                    C + (size_t)(bm + wm * 64 + i * 16) * N + bn + wn * 32 + j * 16,
                    acc[i][j], N, wmma::mem_row_major);
    } else {
        // stage to smem, then gelu + split-bf16 writes
        __syncthreads();
        float* stage = reinterpret_cast<float*>(smraw);   // 128 x 132 fp32 = 67.5 KB
        #pragma unroll
        for (int i = 0; i < 4; i++)
            #pragma unroll
            for (int j = 0; j < 2; j++)
                wmma::store_matrix_sync(
                    stage + (size_t)(wm * 64 + i * 16) * 132 + wn * 32 + j * 16,
                    acc[i][j], 132, wmma::mem_row_major);
        __syncthreads();
        #pragma unroll
        for (int e = 0; e < 64; e++) {
            const int idx = tid + e * 256;      // 0..16383
            const int row = idx >> 7, col = idx & 127;
            const float gv = gelu_exact(stage[row * 132 + col]);
            bf16 hi, lo;
            split_bf16(gv, hi, lo);
            const size_t gi = (size_t)(bm + row) * N + bn + col;
            Chi[gi] = hi;
            Clo[gi] = lo;
        }
    }
}

// ---------------- Flash attention (causal), 64q x 64k tiles, hs=64 (SIMT fp32) ----------------
#define FPAD 68

__global__ __launch_bounds__(256) void flash_kernel(
    const float* __restrict__ qkv, bf16* __restrict__ out_hi, bf16* __restrict__ out_lo) {
    extern __shared__ float smf[];
    float* Qs = smf;
    float* Ks = smf + 64 * FPAD;
    float* Vs = smf + 2 * 64 * FPAD;
    float* Ps = smf + 3 * 64 * FPAD;

    const int tid = threadIdx.x;
    const int tx = tid & 15;
    const int ty = tid >> 4;
    const int qb = blockIdx.x;
    const int hd = blockIdx.y;

    {
        const int r0 = tid >> 4;
        const int c4 = (tid & 15) << 2;
        #pragma unroll
        for (int i = 0; i < 4; i++) {
            const int m = r0 + i * 16;
            const float4 q = *reinterpret_cast<const float4*>(
                qkv + (size_t)(qb * 64 + m) * C3 + hd * HS + c4);
            Qs[(c4 + 0) * FPAD + m] = q.x;
            Qs[(c4 + 1) * FPAD + m] = q.y;
            Qs[(c4 + 2) * FPAD + m] = q.z;
            Qs[(c4 + 3) * FPAD + m] = q.w;
        }
    }

    float mi[4], li[4], o[4][4];
    #pragma unroll
    for (int i = 0; i < 4; i++) {
        mi[i] = -1e30f; li[i] = 0.f;
        #pragma unroll
        for (int j = 0; j < 4; j++) o[i][j] = 0.f;
    }

    for (int kt = 0; kt <= qb; kt++) {
        __syncthreads();
        {
            const int r0 = tid >> 4;
            const int c4 = (tid & 15) << 2;
            #pragma unroll
            for (int i = 0; i < 4; i++) {
                const int n = r0 + i * 16;
                const size_t base = (size_t)(kt * 64 + n) * C3 + hd * HS + c4;
                const float4 k = *reinterpret_cast<const float4*>(qkv + base + EMB);
                Ks[(c4 + 0) * FPAD + n] = k.x;
                Ks[(c4 + 1) * FPAD + n] = k.y;
                Ks[(c4 + 2) * FPAD + n] = k.z;
                Ks[(c4 + 3) * FPAD + n] = k.w;
                const float4 vv = *reinterpret_cast<const float4*>(qkv + base + 2 * EMB);
                *reinterpret_cast<float4*>(Vs + n * FPAD + c4) = vv;
            }
        }
        __syncthreads();

        float s[4][4];
        #pragma unroll
        for (int i = 0; i < 4; i++)
            #pragma unroll
            for (int j = 0; j < 4; j++) s[i][j] = 0.f;
        #pragma unroll 8
        for (int kk = 0; kk < 64; kk++) {
            float a[4], b[4];
            *reinterpret_cast<float4*>(a) = *reinterpret_cast<float4*>(Qs + kk * FPAD + ty * 4);
            *reinterpret_cast<float4*>(b) = *reinterpret_cast<float4*>(Ks + kk * FPAD + tx * 4);
            #pragma unroll
            for (int i = 0; i < 4; i++)
                #pragma unroll
                for (int j = 0; j < 4; j++)
                    s[i][j] = fmaf(a[i], b[j], s[i][j]);
        }
        const bool diag = (kt == qb);
        #pragma unroll
        for (int i = 0; i < 4; i++)
            #pragma unroll
            for (int j = 0; j < 4; j++) {
                s[i][j] *= 0.125f;
                if (diag && (tx * 4 + j) > (ty * 4 + i)) s[i][j] = -1e30f;
            }

        #pragma unroll
        for (int i = 0; i < 4; i++) {
            float mx = fmaxf(fmaxf(s[i][0], s[i][1]), fmaxf(s[i][2], s[i][3]));
            #pragma unroll
            for (int off = 8; off > 0; off >>= 1)
                mx = fmaxf(mx, __shfl_xor_sync(0xffffffffu, mx, off));
            const float mn = fmaxf(mi[i], mx);
            const float alpha = __expf(mi[i] - mn);
            float rs = 0.f;
            #pragma unroll
            for (int j = 0; j < 4; j++) {
                const float p = __expf(s[i][j] - mn);
                s[i][j] = p;
                rs += p;
            }
            #pragma unroll
            for (int off = 8; off > 0; off >>= 1)
                rs += __shfl_xor_sync(0xffffffffu, rs, off);
            li[i] = li[i] * alpha + rs;
            mi[i] = mn;
            #pragma unroll
            for (int j = 0; j < 4; j++) o[i][j] *= alpha;
            #pragma unroll
            for (int j = 0; j < 4; j++)
                Ps[(tx * 4 + j) * FPAD + ty * 4 + i] = s[i][j];
        }
        __syncthreads();

        #pragma unroll 8
        for (int kk = 0; kk < 64; kk++) {
            float p[4], v[4];
            *reinterpret_cast<float4*>(p) = *reinterpret_cast<float4*>(Ps + kk * FPAD + ty * 4);
            *reinterpret_cast<float4*>(v) = *reinterpret_cast<float4*>(Vs + kk * FPAD + tx * 4);
            #pragma unroll
            for (int i = 0; i < 4; i++)
                #pragma unroll
                for (int j = 0; j < 4; j++)
                    o[i][j] = fmaf(p[i], v[j], o[i][j]);
        }
    }

    #pragma unroll
    for (int i = 0; i < 4; i++) {
        const float inv = 1.0f / li[i];
        const size_t row = (size_t)(qb * 64 + ty * 4 + i);
        const size_t cb = row * EMB + hd * HS + tx * 4;
        #pragma unroll
        for (int j = 0; j < 4; j++) {
            const float v = o[i][j] * inv;
            bf16 hi, lo;
            split_bf16(v, hi, lo);
            out_hi[cb + j] = hi;
            out_lo[cb + j] = lo;
        }
    }
}

// ---------------- launch ----------------
extern "C" void kernel_launch(void* const* d_in, const int* in_sizes, int n_in,
                              void* d_out, int out_size) {
    const float* x           = (const float*)d_in[0];
    const float* w_qkv       = (const float*)d_in[1];
    const float* w_attn_proj = (const float*)d_in[2];
    const float* w_fc        = (const float*)d_in[3];
    const float* w_mlp_proj  = (const float*)d_in[4];
    const float* ln1_w       = (const float*)d_in[5];
    const float* ln2_w       = (const float*)d_in[6];
    float* out = (float*)d_out;

    bf16 *p_h_hi, *p_h_lo, *p_attn_hi, *p_attn_lo, *p_fc_hi, *p_fc_lo;
    bf16 *p_wqkv_hi, *p_wqkv_lo, *p_wproj_hi, *p_wproj_lo;
    bf16 *p_wfc_hi, *p_wfc_lo, *p_wmlp_hi, *p_wmlp_lo;
    float *p_qkv, *p_x1;
    cudaGetSymbolAddress((void**)&p_h_hi, g_h_hi);
    cudaGetSymbolAddress((void**)&p_h_lo, g_h_lo);
    cudaGetSymbolAddress((void**)&p_qkv, g_qkv);
    cudaGetSymbolAddress((void**)&p_attn_hi, g_attn_hi);
    cudaGetSymbolAddress((void**)&p_attn_lo, g_attn_lo);
    cudaGetSymbolAddress((void**)&p_x1, g_x1);
    cudaGetSymbolAddress((void**)&p_fc_hi, g_fc_hi);
    cudaGetSymbolAddress((void**)&p_fc_lo, g_fc_lo);
    cudaGetSymbolAddress((void**)&p_wqkv_hi, g_wqkv_hi);
    cudaGetSymbolAddress((void**)&p_wqkv_lo, g_wqkv_lo);
    cudaGetSymbolAddress((void**)&p_wproj_hi, g_wproj_hi);
    cudaGetSymbolAddress((void**)&p_wproj_lo, g_wproj_lo);
    cudaGetSymbolAddress((void**)&p_wfc_hi, g_wfc_hi);
    cudaGetSymbolAddress((void**)&p_wfc_lo, g_wfc_lo);
    cudaGetSymbolAddress((void**)&p_wmlp_hi, g_wmlp_hi);
    cudaGetSymbolAddress((void**)&p_wmlp_lo, g_wmlp_lo);

    const int gemm_smem = 4 * 128 * APAD * (int)sizeof(bf16);  // 73,728 B
    cudaFuncSetAttribute(mma_gemm<0>, cudaFuncAttributeMaxDynamicSharedMemorySize, gemm_smem);
    cudaFuncSetAttribute(mma_gemm<1>, cudaFuncAttributeMaxDynamicSharedMemorySize, gemm_smem);
    cudaFuncSetAttribute(mma_gemm<2>, cudaFuncAttributeMaxDynamicSharedMemorySize, gemm_smem);
    const int flash_smem = 4 * 64 * FPAD * (int)sizeof(float);
    cudaFuncSetAttribute(flash_kernel, cudaFuncAttributeMaxDynamicSharedMemorySize, flash_smem);

    // 0. weight transpose + split
    wt_split_kernel<<<dim3(C3 / 32, EMB / 32), 256>>>(w_qkv, p_wqkv_hi, p_wqkv_lo, EMB, C3);
    wt_split_kernel<<<dim3(EMB / 32, EMB / 32), 256>>>(w_attn_proj, p_wproj_hi, p_wproj_lo, EMB, EMB);
    wt_split_kernel<<<dim3(CFC / 32, EMB / 32), 256>>>(w_fc, p_wfc_hi, p_wfc_lo, EMB, CFC);
    wt_split_kernel<<<dim3(EMB / 32, CFC / 32), 256>>>(w_mlp_proj, p_wmlp_hi, p_wmlp_lo, CFC, EMB);

    // 1. h = LN(x, ln1)
    ln_kernel<<<SEQ, 256>>>(x, ln1_w, p_h_hi, p_h_lo);
    // 2. qkv = h @ w_qkv
    mma_gemm<0><<<dim3(C3 / 128, SEQ / 128), 256, gemm_smem>>>(
        p_h_hi, p_h_lo, p_wqkv_hi, p_wqkv_lo, nullptr, p_qkv, nullptr, nullptr, SEQ, C3, EMB);
    // 3. attention
    flash_kernel<<<dim3(SEQ / 64, NHEAD), 256, flash_smem>>>(p_qkv, p_attn_hi, p_attn_lo);
    // 4. x1 = x + attn @ w_attn_proj
    mma_gemm<1><<<dim3(EMB / 128, SEQ / 128), 256, gemm_smem>>>(
        p_attn_hi, p_attn_lo, p_wproj_hi, p_wproj_lo, x, p_x1, nullptr, nullptr, SEQ, EMB, EMB);
    // 5. h = LN(x1, ln2)
    ln_kernel<<<SEQ, 256>>>(p_x1, ln2_w, p_h_hi, p_h_lo);
    // 6. fc = gelu(h @ w_fc)
    mma_gemm<2><<<dim3(CFC / 128, SEQ / 128), 256, gemm_smem>>>(
        p_h_hi, p_h_lo, p_wfc_hi, p_wfc_lo, nullptr, nullptr, p_fc_hi, p_fc_lo, SEQ, CFC, EMB);
    // 7. out = x1 + fc @ w_mlp_proj
    mma_gemm<1><<<dim3(EMB / 128, SEQ / 128), 256, gemm_smem>>>(
        p_fc_hi, p_fc_lo, p_wmlp_hi, p_wmlp_lo, p_x1, out, nullptr, nullptr, SEQ, EMB, CFC);
}

// round 4
// speedup vs baseline: 2.4701x; 1.4146x over previous
#include <cuda_runtime.h>
#include <cuda_bf16.h>
#include <cuda_fp16.h>
#include <mma.h>
#include <cstdint>
#include <math.h>

using namespace nvcuda;

// Block: B=1, T=4096, C=1024, H=16, hs=64
#define SEQ 4096
#define EMB 1024
#define NHEAD 16
#define HS 64
#define C3 3072
#define CFC 4096

typedef __nv_bfloat16 bf16;

// ---------------- device scratch (no allocations allowed) ----------------
__device__ bf16 g_h_hi[SEQ * EMB], g_h_lo[SEQ * EMB];        // LN out (split)
__device__ float g_qkv[SEQ * C3];                            // qkv fp32
__device__ bf16 g_attn_hi[SEQ * EMB], g_attn_lo[SEQ * EMB];  // attention out (split)
__device__ float g_x1[SEQ * EMB];                            // x + attn_proj
__device__ bf16 g_fc_hi[SEQ * CFC], g_fc_lo[SEQ * CFC];      // gelu(fc) (split)
// transposed + split weights: Wt[n][k]
__device__ bf16 g_wqkv_hi[C3 * EMB], g_wqkv_lo[C3 * EMB];
__device__ bf16 g_wproj_hi[EMB * EMB], g_wproj_lo[EMB * EMB];
__device__ bf16 g_wfc_hi[CFC * EMB], g_wfc_lo[CFC * EMB];
__device__ bf16 g_wmlp_hi[EMB * CFC], g_wmlp_lo[EMB * CFC];

__device__ __forceinline__ void split_bf16(float v, bf16& hi, bf16& lo) {
    hi = __float2bfloat16(v);
    lo = __float2bfloat16(v - __bfloat162float(hi));
}
__device__ __forceinline__ float gelu_exact(float v) {
    return 0.5f * v * (1.0f + erff(v * 0.70710678118654752440f));
}

// ---- cp.async helpers ----
__device__ __forceinline__ uint32_t smem_u32(const void* p) {
    uint32_t a;
    asm("{ .reg .u64 t; cvta.to.shared.u64 t, %1; cvt.u32.u64 %0, t; }" : "=r"(a) : "l"(p));
    return a;
}
__device__ __forceinline__ void cp16(void* sp, const void* gp) {
    asm volatile("cp.async.cg.shared.global [%0], [%1], 16;" :: "r"(smem_u32(sp)), "l"(gp));
}
__device__ __forceinline__ void cp_commit() {
    asm volatile("cp.async.commit_group;" ::: "memory");
}
__device__ __forceinline__ void cp_wait0() {
    asm volatile("cp.async.wait_group 0;" ::: "memory");
}
__device__ __forceinline__ void cp_wait1() {
    asm volatile("cp.async.wait_group 1;" ::: "memory");
}

// ---------------- LayerNorm -> split bf16 ----------------
__global__ void ln_kernel(const float* __restrict__ x, const float* __restrict__ w,
                          bf16* __restrict__ out_hi, bf16* __restrict__ out_lo) {
    const int row = blockIdx.x;
    const int tid = threadIdx.x;  // 256, 4 floats each
    const float4 v = reinterpret_cast<const float4*>(x + (size_t)row * EMB)[tid];

    float s = v.x + v.y + v.z + v.w;
    float q = v.x * v.x + v.y * v.y + v.z * v.z + v.w * v.w;
    #pragma unroll
    for (int off = 16; off > 0; off >>= 1) {
        s += __shfl_xor_sync(0xffffffffu, s, off);
        q += __shfl_xor_sync(0xffffffffu, q, off);
    }
    __shared__ float ws[8], wq[8], s_mean, s_rstd;
    const int wid = tid >> 5, lane = tid & 31;
    if (lane == 0) { ws[wid] = s; wq[wid] = q; }
    __syncthreads();
    if (tid == 0) {
        float S = 0.f, Q = 0.f;
        #pragma unroll
        for (int i = 0; i < 8; i++) { S += ws[i]; Q += wq[i]; }
        float mean = S * (1.0f / EMB);
        float var = Q * (1.0f / EMB) - mean * mean;
        s_mean = mean;
        s_rstd = rsqrtf(var + 1e-5f);
    }
    __syncthreads();
    const float mean = s_mean, rstd = s_rstd;
    const float4 g = reinterpret_cast<const float4*>(w)[tid];
    float o[4] = {(v.x - mean) * rstd * g.x, (v.y - mean) * rstd * g.y,
                  (v.z - mean) * rstd * g.z, (v.w - mean) * rstd * g.w};
    const size_t base = (size_t)row * EMB + tid * 4;
    #pragma unroll
    for (int i = 0; i < 4; i++) {
        bf16 hi, lo;
        split_bf16(o[i], hi, lo);
        out_hi[base + i] = hi;
        out_lo[base + i] = lo;
    }
}

// ---------------- weight transpose + split: W[K,N] fp32 -> Wt_hi/lo[N,K] bf16 ----------------
__global__ __launch_bounds__(256) void wt_split_kernel(const float* __restrict__ W,
                                                       bf16* __restrict__ th,
                                                       bf16* __restrict__ tl,
                                                       int K, int N) {
    __shared__ float tile[32][33];
    const int bn = blockIdx.x * 32;
    const int bk = blockIdx.y * 32;
    const int tx = threadIdx.x & 31, ty = threadIdx.x >> 5;
    #pragma unroll
    for (int r = ty; r < 32; r += 8)
        tile[r][tx] = W[(size_t)(bk + r) * N + bn + tx];
    __syncthreads();
    #pragma unroll
    for (int r = ty; r < 32; r += 8) {
        const float v = tile[tx][r];  // = W[bk+tx][bn+r]
        bf16 hi, lo;
        split_bf16(v, hi, lo);
        const size_t o = (size_t)(bn + r) * K + bk + tx;
        th[o] = hi;
        tl[o] = lo;
    }
}

// ---------------- WMMA GEMM (double-buffered cp.async): C = A @ Wt^T, bf16x3 ----------------
// EPI: 0 = plain fp32 C, 1 = C = R + acc, 2 = gelu(acc)->split bf16
#define KC2 32
#define SPAD 40                     // smem row stride (bf16 elems)
#define SLAB (128 * SPAD)           // elems per slab
#define STAGE_ELEMS (4 * SLAB)      // Ah Al Bh Bl

template <int EPI>
__global__ __launch_bounds__(256, 2) void mma_gemm(
    const bf16* __restrict__ Ah, const bf16* __restrict__ Al,
    const bf16* __restrict__ Bh, const bf16* __restrict__ Bl,
    const float* __restrict__ R, float* __restrict__ C,
    bf16* __restrict__ Chi, bf16* __restrict__ Clo,
    int M, int N, int K) {
    extern __shared__ char smraw[];
    bf16* sm = reinterpret_cast<bf16*>(smraw);

    const int tid = threadIdx.x;
    const int wid = tid >> 5;
    const int wm = wid & 1;        // 2 warps in M  (64 rows each)
    const int wn = wid >> 1;       // 4 warps in N  (32 cols each)
    const int bm = blockIdx.y * 128, bn = blockIdx.x * 128;

    wmma::fragment<wmma::accumulator, 16, 16, 16, float> acc[4][2];
    if (EPI == 1) {
        #pragma unroll
        for (int i = 0; i < 4; i++)
            #pragma unroll
            for (int j = 0; j < 2; j++)
                wmma::load_matrix_sync(
                    acc[i][j],
                    R + (size_t)(bm + wm * 64 + i * 16) * N + bn + wn * 32 + j * 16,
                    N, wmma::mem_row_major);
    } else {
        #pragma unroll
        for (int i = 0; i < 4; i++)
            #pragma unroll
            for (int j = 0; j < 2; j++)
                wmma::fill_fragment(acc[i][j], 0.0f);
    }

    const int NC = K / KC2;

    // stage loader: 512 16B ops per slab-pair group; thread does idx = tid, tid+256
    auto load_stage = [&](int buf, int k0) {
        bf16* st = sm + buf * STAGE_ELEMS;
        #pragma unroll
        for (int o = 0; o < 2; o++) {
            const int idx = tid + o * 256;      // 0..511
            const int row = idx >> 2, seg = idx & 3;
            const int soff = row * SPAD + seg * 8;
            const size_t ga = (size_t)(bm + row) * K + k0 + seg * 8;
            const size_t gb = (size_t)(bn + row) * K + k0 + seg * 8;
            cp16(st + soff,            Ah + ga);
            cp16(st + SLAB + soff,     Al + ga);
            cp16(st + 2 * SLAB + soff, Bh + gb);
            cp16(st + 3 * SLAB + soff, Bl + gb);
        }
    };

    load_stage(0, 0);
    cp_commit();

    for (int c = 0; c < NC; c++) {
        if (c + 1 < NC) {
            load_stage((c + 1) & 1, (c + 1) * KC2);
            cp_commit();
            cp_wait1();
        } else {
            cp_wait0();
        }
        __syncthreads();

        bf16* st = sm + (c & 1) * STAGE_ELEMS;
        bf16* sAh = st;
        bf16* sAl = st + SLAB;
        bf16* sBh = st + 2 * SLAB;
        bf16* sBl = st + 3 * SLAB;

        #pragma unroll
        for (int kk = 0; kk < KC2 / 16; kk++) {
            wmma::fragment<wmma::matrix_b, 16, 16, 16, bf16, wmma::col_major> b_hi[2], b_lo[2];
            #pragma unroll
            for (int j = 0; j < 2; j++) {
                const int nb = (wn * 32 + j * 16) * SPAD + kk * 16;
                wmma::load_matrix_sync(b_hi[j], sBh + nb, SPAD);
                wmma::load_matrix_sync(b_lo[j], sBl + nb, SPAD);
            }
            #pragma unroll
            for (int i = 0; i < 4; i++) {
                wmma::fragment<wmma::matrix_a, 16, 16, 16, bf16, wmma::row_major> a_hi, a_lo;
                const int ab = (wm * 64 + i * 16) * SPAD + kk * 16;
                wmma::load_matrix_sync(a_hi, sAh + ab, SPAD);
                wmma::load_matrix_sync(a_lo, sAl + ab, SPAD);
                #pragma unroll
                for (int j = 0; j < 2; j++) {
                    wmma::mma_sync(acc[i][j], a_hi, b_hi[j], acc[i][j]);
                    wmma::mma_sync(acc[i][j], a_hi, b_lo[j], acc[i][j]);
                    wmma::mma_sync(acc[i][j], a_lo, b_hi[j], acc[i][j]);
                }
            }
        }
        __syncthreads();
    }

    if (EPI != 2) {
        #pragma unroll
        for (int i = 0; i < 4; i++)
            #pragma unroll
            for (int j = 0; j < 2; j++)
                wmma::store_matrix_sync(
                    C + (size_t)(bm + wm * 64 + i * 16) * N + bn + wn * 32 + j * 16,
                    acc[i][j], N, wmma::mem_row_major);
    } else {
        float* stage = reinterpret_cast<float*>(smraw);   // 128 x 132 fp32
        #pragma unroll
        for (int i = 0; i < 4; i++)
            #pragma unroll
            for (int j = 0; j < 2; j++)
                wmma::store_matrix_sync(
                    stage + (size_t)(wm * 64 + i * 16) * 132 + wn * 32 + j * 16,
                    acc[i][j], 132, wmma::mem_row_major);
        __syncthreads();
        #pragma unroll
        for (int e = 0; e < 64; e++) {
            const int idx = tid + e * 256;
            const int row = idx >> 7, col = idx & 127;
            const float gv = gelu_exact(stage[row * 132 + col]);
            bf16 hi, lo;
            split_bf16(gv, hi, lo);
            const size_t gi = (size_t)(bm + row) * N + bn + col;
            Chi[gi] = hi;
            Clo[gi] = lo;
        }
    }
}

// ---------------- Tensor-core flash attention (causal), 64q x 64k, hs=64 ----------------
// S = Qh @ (Kh + Kl)^T (fp16 2-pass), softmax fp32 in smem, O += P @ (Vh + Vl)
#define QPAD 72

__global__ __launch_bounds__(256, 2) void flash_tc(
    const float* __restrict__ qkv, bf16* __restrict__ out_hi, bf16* __restrict__ out_lo) {
    extern __shared__ char smraw[];
    __half* Qh = reinterpret_cast<__half*>(smraw);   // 64x72
    __half* Kh = Qh + 64 * QPAD;
    __half* Kl = Kh + 64 * QPAD;
    __half* Vh = Kl + 64 * QPAD;
    __half* Vl = Vh + 64 * QPAD;
    __half* Pm = Vl + 64 * QPAD;
    float* Sf = reinterpret_cast<float*>(Pm + 64 * QPAD);  // 64x72 fp32
    float* Of = Sf + 64 * QPAD;                            // 64x72 fp32

    const int tid = threadIdx.x;
    const int wid = tid >> 5;
    const int wm = wid >> 2;   // 2 warps in M (32 rows each)
    const int wn = wid & 3;    // 4 warps in N (16 cols each)
    const int qb = blockIdx.x;
    const int hd = blockIdx.y;

    // load Q tile (fp16 hi only), init O = 0
    for (int i = tid; i < 4096; i += 256) {
        const int r = i >> 6, c = i & 63;
        const float q = qkv[(size_t)(qb * 64 + r) * C3 + hd * HS + c];
        Qh[r * QPAD + c] = __float2half(q);
        Of[r * QPAD + c] = 0.f;
    }

    float mi = -1e30f, li = 0.f;
    const int row = tid >> 2, quad = tid & 3;

    for (int kt = 0; kt <= qb; kt++) {
        __syncthreads();
        // load + split K, V tiles
        for (int i = tid; i < 4096; i += 256) {
            const int r = i >> 6, c = i & 63;
            const size_t base = (size_t)(kt * 64 + r) * C3 + hd * HS + c;
            const float k = qkv[base + EMB];
            const __half kh = __float2half(k);
            Kh[r * QPAD + c] = kh;
            Kl[r * QPAD + c] = __float2half(k - __half2float(kh));
            const float v = qkv[base + 2 * EMB];
            const __half vh = __float2half(v);
            Vh[r * QPAD + c] = vh;
            Vl[r * QPAD + c] = __float2half(v - __half2float(vh));
        }
        __syncthreads();

        // S = Qh @ K^T (K split 2-pass)
        {
            wmma::fragment<wmma::accumulator, 16, 16, 16, float> sa[2];
            #pragma unroll
            for (int i = 0; i < 2; i++) wmma::fill_fragment(sa[i], 0.0f);
            #pragma unroll
            for (int kk = 0; kk < 4; kk++) {
                wmma::fragment<wmma::matrix_b, 16, 16, 16, __half, wmma::col_major> bh, bl;
                const int nb = (wn * 16) * QPAD + kk * 16;
                wmma::load_matrix_sync(bh, Kh + nb, QPAD);
                wmma::load_matrix_sync(bl, Kl + nb, QPAD);
                #pragma unroll
                for (int i = 0; i < 2; i++) {
                    wmma::fragment<wmma::matrix_a, 16, 16, 16, __half, wmma::row_major> a;
                    wmma::load_matrix_sync(a, Qh + (wm * 32 + i * 16) * QPAD + kk * 16, QPAD);
                    wmma::mma_sync(sa[i], a, bh, sa[i]);
                    wmma::mma_sync(sa[i], a, bl, sa[i]);
                }
            }
            #pragma unroll
            for (int i = 0; i < 2; i++)
                wmma::store_matrix_sync(Sf + (wm * 32 + i * 16) * QPAD + wn * 16,
                                        sa[i], QPAD, wmma::mem_row_major);
        }
        __syncthreads();

        // softmax (online): thread -> (row, quad of 16 cols)
        {
            const bool diag = (kt == qb);
            float s[16];
            float mx = -1e30f;
            #pragma unroll
            for (int j = 0; j < 16; j++) {
                float v = Sf[row * QPAD + quad * 16 + j] * 0.125f;
                if (diag && (quad * 16 + j) > row) v = -1e30f;
                s[j] = v;
                mx = fmaxf(mx, v);
            }
            mx = fmaxf(mx, __shfl_xor_sync(0xffffffffu, mx, 1));
            mx = fmaxf(mx, __shfl_xor_sync(0xffffffffu, mx, 2));
            const float mn = fmaxf(mi, mx);
            const float alpha = __expf(mi - mn);
            float rs = 0.f;
            #pragma unroll
            for (int j = 0; j < 16; j++) {
                const float p = __expf(s[j] - mn);
                Pm[row * QPAD + quad * 16 + j] = __float2half(p);
                rs += p;
            }
            rs += __shfl_xor_sync(0xffffffffu, rs, 1);
            rs += __shfl_xor_sync(0xffffffffu, rs, 2);
            li = li * alpha + rs;
            mi = mn;
            #pragma unroll
            for (int j = 0; j < 16; j++)
                Of[row * QPAD + quad * 16 + j] *= alpha;
        }
        __syncthreads();

        // O += P @ V (V split 2-pass)
        {
            wmma::fragment<wmma::accumulator, 16, 16, 16, float> oa[2];
            #pragma unroll
            for (int i = 0; i < 2; i++)
                wmma::load_matrix_sync(oa[i], Of + (wm * 32 + i * 16) * QPAD + wn * 16,
                                       QPAD, wmma::mem_row_major);
            #pragma unroll
            for (int kk = 0; kk < 4; kk++) {
                wmma::fragment<wmma::matrix_b, 16, 16, 16, __half, wmma::row_major> bh, bl;
                const int vb = (kk * 16) * QPAD + wn * 16;
                wmma::load_matrix_sync(bh, Vh + vb, QPAD);
                wmma::load_matrix_sync(bl, Vl + vb, QPAD);
                #pragma unroll
                for (int i = 0; i < 2; i++) {
                    wmma::fragment<wmma::matrix_a, 16, 16, 16, __half, wmma::row_major> a;
                    wmma::load_matrix_sync(a, Pm + (wm * 32 + i * 16) * QPAD + kk * 16, QPAD);
                    wmma::mma_sync(oa[i], a, bh, oa[i]);
                    wmma::mma_sync(oa[i], a, bl, oa[i]);
                }
            }
            #pragma unroll
            for (int i = 0; i < 2; i++)
                wmma::store_matrix_sync(Of + (wm * 32 + i * 16) * QPAD + wn * 16,
                                        oa[i], QPAD, wmma::mem_row_major);
        }
    }
    __syncthreads();

    // finalize: attn = O / li, split bf16
    {
        const float inv = 1.0f / li;
        #pragma unroll
        for (int j = 0; j < 16; j++) {
            const float v = Of[row * QPAD + quad * 16 + j] * inv;
            bf16 hi, lo;
            split_bf16(v, hi, lo);
            const size_t o = (size_t)(qb * 64 + row) * EMB + hd * HS + quad * 16 + j;
            out_hi[o] = hi;
            out_lo[o] = lo;
        }
    }
}

// ---------------- launch ----------------
extern "C" void kernel_launch(void* const* d_in, const int* in_sizes, int n_in,
                              void* d_out, int out_size) {
    const float* x           = (const float*)d_in[0];
    const float* w_qkv       = (const float*)d_in[1];
    const float* w_attn_proj = (const float*)d_in[2];
    const float* w_fc        = (const float*)d_in[3];
    const float* w_mlp_proj  = (const float*)d_in[4];
    const float* ln1_w       = (const float*)d_in[5];
    const float* ln2_w       = (const float*)d_in[6];
    float* out = (float*)d_out;

    bf16 *p_h_hi, *p_h_lo, *p_attn_hi, *p_attn_lo, *p_fc_hi, *p_fc_lo;
    bf16 *p_wqkv_hi, *p_wqkv_lo, *p_wproj_hi, *p_wproj_lo;
    bf16 *p_wfc_hi, *p_wfc_lo, *p_wmlp_hi, *p_wmlp_lo;
    float *p_qkv, *p_x1;
    cudaGetSymbolAddress((void**)&p_h_hi, g_h_hi);
    cudaGetSymbolAddress((void**)&p_h_lo, g_h_lo);
    cudaGetSymbolAddress((void**)&p_qkv, g_qkv);
    cudaGetSymbolAddress((void**)&p_attn_hi, g_attn_hi);
    cudaGetSymbolAddress((void**)&p_attn_lo, g_attn_lo);
    cudaGetSymbolAddress((void**)&p_x1, g_x1);
    cudaGetSymbolAddress((void**)&p_fc_hi, g_fc_hi);
    cudaGetSymbolAddress((void**)&p_fc_lo, g_fc_lo);
    cudaGetSymbolAddress((void**)&p_wqkv_hi, g_wqkv_hi);
    cudaGetSymbolAddress((void**)&p_wqkv_lo, g_wqkv_lo);
    cudaGetSymbolAddress((void**)&p_wproj_hi, g_wproj_hi);
    cudaGetSymbolAddress((void**)&p_wproj_lo, g_wproj_lo);
    cudaGetSymbolAddress((void**)&p_wfc_hi, g_wfc_hi);
    cudaGetSymbolAddress((void**)&p_wfc_lo, g_wfc_lo);
    cudaGetSymbolAddress((void**)&p_wmlp_hi, g_wmlp_hi);
    cudaGetSymbolAddress((void**)&p_wmlp_lo, g_wmlp_lo);

    const int gemm_smem = 2 * STAGE_ELEMS * (int)sizeof(bf16);          // 81,920 B
    cudaFuncSetAttribute(mma_gemm<0>, cudaFuncAttributeMaxDynamicSharedMemorySize, gemm_smem);
    cudaFuncSetAttribute(mma_gemm<1>, cudaFuncAttributeMaxDynamicSharedMemorySize, gemm_smem);
    cudaFuncSetAttribute(mma_gemm<2>, cudaFuncAttributeMaxDynamicSharedMemorySize, gemm_smem);
    const int flash_smem = 64 * QPAD * (6 * (int)sizeof(__half) + 2 * (int)sizeof(float));  // 92,160 B
    cudaFuncSetAttribute(flash_tc, cudaFuncAttributeMaxDynamicSharedMemorySize, flash_smem);

    // 0. weight transpose + split
    wt_split_kernel<<<dim3(C3 / 32, EMB / 32), 256>>>(w_qkv, p_wqkv_hi, p_wqkv_lo, EMB, C3);
    wt_split_kernel<<<dim3(EMB / 32, EMB / 32), 256>>>(w_attn_proj, p_wproj_hi, p_wproj_lo, EMB, EMB);
    wt_split_kernel<<<dim3(CFC / 32, EMB / 32), 256>>>(w_fc, p_wfc_hi, p_wfc_lo, EMB, CFC);
    wt_split_kernel<<<dim3(EMB / 32, CFC / 32), 256>>>(w_mlp_proj, p_wmlp_hi, p_wmlp_lo, CFC, EMB);

    // 1. h = LN(x, ln1)
    ln_kernel<<<SEQ, 256>>>(x, ln1_w, p_h_hi, p_h_lo);
    // 2. qkv = h @ w_qkv
    mma_gemm<0><<<dim3(C3 / 128, SEQ / 128), 256, gemm_smem>>>(
        p_h_hi, p_h_lo, p_wqkv_hi, p_wqkv_lo, nullptr, p_qkv, nullptr, nullptr, SEQ, C3, EMB);
    // 3. attention (tensor core)
    flash_tc<<<dim3(SEQ / 64, NHEAD), 256, flash_smem>>>(p_qkv, p_attn_hi, p_attn_lo);
    // 4. x1 = x + attn @ w_attn_proj
    mma_gemm<1><<<dim3(EMB / 128, SEQ / 128), 256, gemm_smem>>>(
        p_attn_hi, p_attn_lo, p_wproj_hi, p_wproj_lo, x, p_x1, nullptr, nullptr, SEQ, EMB, EMB);
    // 5. h = LN(x1, ln2)
    ln_kernel<<<SEQ, 256>>>(p_x1, ln2_w, p_h_hi, p_h_lo);
    // 6. fc = gelu(h @ w_fc)
    mma_gemm<2><<<dim3(CFC / 128, SEQ / 128), 256, gemm_smem>>>(
        p_h_hi, p_h_lo, p_wfc_hi, p_wfc_lo, nullptr, nullptr, p_fc_hi, p_fc_lo, SEQ, CFC, EMB);
    // 7. out = x1 + fc @ w_mlp_proj
    mma_gemm<1><<<dim3(EMB / 128, SEQ / 128), 256, gemm_smem>>>(
        p_fc_hi, p_fc_lo, p_wmlp_hi, p_wmlp_lo, p_x1, out, nullptr, nullptr, SEQ, EMB, CFC);
}